// round 15
// baseline (speedup 1.0000x reference)
#include <cuda_runtime.h>
#include <cuda_bf16.h>
#include <math.h>

#define NB    2
#define LSEQ  2048
#define EMB   1024
#define HEADS 16
#define HDIM  64

// ---------------- scratch (no allocations allowed) ----------------
__device__ __align__(16) __nv_bfloat16 g_k[NB * LSEQ * EMB];
__device__ __align__(16) __nv_bfloat16 g_v[NB * LSEQ * EMB];
__device__ __align__(16) __nv_bfloat16 g_att[NB * LSEQ * EMB];
__device__ __align__(16) __nv_bfloat16 g_wo[EMB * EMB];

// ---------------- helpers ----------------
__device__ __forceinline__ unsigned su32(const void* p) {
    return (unsigned)__cvta_generic_to_shared(p);
}
__device__ __forceinline__ unsigned packbf(float lo, float hi) {
    __nv_bfloat162 t = __floats2bfloat162_rn(lo, hi);   // .x = lo (low 16 bits)
    return *reinterpret_cast<unsigned*>(&t);
}
__device__ __forceinline__ unsigned ex2b(unsigned x) {   // exp2 on packed bf16x2
    unsigned r;
    asm("ex2.approx.ftz.bf16x2 %0, %1;" : "=r"(r) : "r"(x));
    return r;
}
// D(16x8,f32) += A(16x16,bf16) * B(16x8,bf16)
__device__ __forceinline__ void mma16(float* c, const unsigned* a, unsigned b0, unsigned b1) {
    asm volatile(
        "mma.sync.aligned.m16n8k16.row.col.f32.bf16.bf16.f32 "
        "{%0,%1,%2,%3}, {%4,%5,%6,%7}, {%8,%9}, {%0,%1,%2,%3};\n"
        : "+f"(c[0]), "+f"(c[1]), "+f"(c[2]), "+f"(c[3])
        : "r"(a[0]), "r"(a[1]), "r"(a[2]), "r"(a[3]), "r"(b0), "r"(b1));
}
__device__ __forceinline__ void ldsm4(unsigned& a, unsigned& b, unsigned& c, unsigned& d, unsigned addr) {
    asm volatile("ldmatrix.sync.aligned.m8n8.x4.shared.b16 {%0,%1,%2,%3}, [%4];"
                 : "=r"(a), "=r"(b), "=r"(c), "=r"(d) : "r"(addr));
}
__device__ __forceinline__ void ldsm4t(unsigned& a, unsigned& b, unsigned& c, unsigned& d, unsigned addr) {
    asm volatile("ldmatrix.sync.aligned.m8n8.x4.trans.shared.b16 {%0,%1,%2,%3}, [%4];"
                 : "=r"(a), "=r"(b), "=r"(c), "=r"(d) : "r"(addr));
}
__device__ __forceinline__ void cpasync16(unsigned dst, const void* src) {
    asm volatile("cp.async.cg.shared.global [%0], [%1], 16;" :: "r"(dst), "l"(src));
}
__device__ __forceinline__ void cp_commit() { asm volatile("cp.async.commit_group;"); }
__device__ __forceinline__ void cp_wait0() { asm volatile("cp.async.wait_group 0;" ::: "memory"); }
__device__ __forceinline__ void cp_wait1() { asm volatile("cp.async.wait_group 1;" ::: "memory"); }

// fragment offsets for 144B-stride tiles (64 bf16 + 8 pad)
__device__ __forceinline__ unsigned frag_oa(int lane) {   // A-frag / V-trans ldsm.x4
    return ((((lane >> 3) & 1) * 8 + (lane & 7)) * 144) + ((lane >> 4) * 16);
}
__device__ __forceinline__ unsigned frag_ob(int lane) {   // B-frag non-trans ldsm.x4
    return (lane & 7) * 144 + ((lane >> 3) & 3) * 16;
}
// fragment offsets for 80B-stride tiles (32 bf16 + 8 pad)
__device__ __forceinline__ unsigned frag_oa80(int lane) {
    return ((((lane >> 3) & 1) * 8 + (lane & 7)) * 80) + ((lane >> 4) * 16);
}
__device__ __forceinline__ unsigned frag_ob80(int lane) {
    return (lane & 7) * 80 + ((lane >> 3) & 3) * 16;
}

// Load one m16n8k16 A-fragment k-step straight from gmem (fp32 row-major,
// `stride` floats per row) into packed bf16 regs. Lane layout:
//   a0=(row lr,   k 2lc..2lc+1)  a1=(row lr+8, same)
//   a2=(row lr,   k 2lc+8..+9)   a3=(row lr+8, same)
__device__ __forceinline__ void load_afrag(unsigned* a, const float* base,
                                           int stride, int ks, int lr, int lc) {
    const float* p0 = base + (size_t)lr * stride + ks * 16 + 2 * lc;
    const float* p1 = base + (size_t)(lr + 8) * stride + ks * 16 + 2 * lc;
    float2 a0 = *(const float2*)(p0);
    float2 a1 = *(const float2*)(p1);
    float2 a2 = *(const float2*)(p0 + 8);
    float2 a3 = *(const float2*)(p1 + 8);
    a[0] = packbf(a0.x, a0.y);
    a[1] = packbf(a1.x, a1.y);
    a[2] = packbf(a2.x, a2.y);
    a[3] = packbf(a3.x, a3.y);
}

// =================================================================
// Kernel 1: K/V per-head projections (bf16 MMA), bf16 out.
// X loaded gmem->registers directly (no smem staging, no barrier);
// only W (64x64) staged in smem. 256 rows/block, 8 warps x 32 rows.
// grid.y: 0=K, 1=V, 2=Wo fp32->bf16 cvt.  (Q proj fused into attn.)
// =================================================================
__global__ void __launch_bounds__(256) proj_bf16(
    const float* __restrict__ xk, const float* __restrict__ Wk, __nv_bfloat16* __restrict__ yk,
    const float* __restrict__ xv, const float* __restrict__ Wv, __nv_bfloat16* __restrict__ yv,
    const float* __restrict__ Wo, __nv_bfloat16* __restrict__ wo16)
{
    if (blockIdx.y == 2) {   // Wo conversion: 256 blocks * 256 thr * 16 = 1M elems
        size_t i = ((size_t)blockIdx.x * 256 + threadIdx.x) * 16;
        float4 a = *(const float4*)(Wo + i);
        float4 b = *(const float4*)(Wo + i + 4);
        float4 c = *(const float4*)(Wo + i + 8);
        float4 d = *(const float4*)(Wo + i + 12);
        uint4 o0, o1;
        o0.x = packbf(a.x, a.y);  o0.y = packbf(a.z, a.w);
        o0.z = packbf(b.x, b.y);  o0.w = packbf(b.z, b.w);
        o1.x = packbf(c.x, c.y);  o1.y = packbf(c.z, c.w);
        o1.z = packbf(d.x, d.y);  o1.w = packbf(d.z, d.w);
        *(uint4*)(wo16 + i)     = o0;
        *(uint4*)(wo16 + i + 8) = o1;
        return;
    }

    __shared__ __align__(16) char sm[9216];   // Ws 64x144 only
    const unsigned smb = su32(sm);

    const float* x; const float* W; __nv_bfloat16* y;
    if (blockIdx.y == 0) { x = xk; W = Wk; y = yk; }
    else                 { x = xv; W = Wv; y = yv; }

    const int tid  = threadIdx.x;
    const int wid  = tid >> 5;
    const int lane = tid & 31;
    const int lr   = lane >> 2;
    const int lc   = lane & 3;
    const int row0 = blockIdx.x * 256;
    const unsigned ob = frag_ob(lane);

    // stage W (64x64 fp32 -> bf16)
    #pragma unroll
    for (int it = 0; it < 4; it++) {
        int i = tid + it * 256;
        int r = i >> 4, g = i & 15;
        float4 v = *(const float4*)(W + (size_t)r * 64 + 4 * g);
        *(uint2*)(sm + r * 144 + g * 8) = make_uint2(packbf(v.x, v.y), packbf(v.z, v.w));
    }
    __syncthreads();

    // X fragments: rows wid*32 .. wid*32+31, loaded directly from gmem
    unsigned aq[2][4][4];
    #pragma unroll
    for (int g = 0; g < 2; g++)
        #pragma unroll
        for (int ks = 0; ks < 4; ks++)
            load_afrag(aq[g][ks], x + (size_t)(row0 + wid * 32 + g * 16) * 64,
                       64, ks, lr, lc);

    float acc[2][8][4];
    #pragma unroll
    for (int g = 0; g < 2; g++)
        #pragma unroll
        for (int nt = 0; nt < 8; nt++)
            #pragma unroll
            for (int j = 0; j < 4; j++) acc[g][nt][j] = 0.f;

    #pragma unroll
    for (int nt = 0; nt < 8; nt++) {
        unsigned b0, b1, b2, b3, c0, c1, c2, c3;
        ldsm4(b0, b1, b2, b3, smb + nt * 1152 + ob);
        ldsm4(c0, c1, c2, c3, smb + nt * 1152 + 64 + ob);
        #pragma unroll
        for (int g = 0; g < 2; g++) {
            mma16(acc[g][nt], aq[g][0], b0, b1);
            mma16(acc[g][nt], aq[g][1], b2, b3);
            mma16(acc[g][nt], aq[g][2], c0, c1);
            mma16(acc[g][nt], aq[g][3], c2, c3);
        }
    }

    unsigned* y32 = (unsigned*)y;
    #pragma unroll
    for (int g = 0; g < 2; g++) {
        const int rlo = row0 + wid * 32 + g * 16 + lr;
        #pragma unroll
        for (int nt = 0; nt < 8; nt++) {
            y32[(size_t)rlo * 32 + nt * 4 + lc] = packbf(acc[g][nt][0], acc[g][nt][1]);
            y32[(size_t)(rlo + 8) * 32 + nt * 4 + lc] = packbf(acc[g][nt][2], acc[g][nt][3]);
        }
    }
}

// =================================================================
// Kernel 2: flash attention with FUSED Q projection (round-11 body).
// Prologue: Xq loaded gmem->registers directly; only Wq staged in smem.
// 4 warps x 32 q-rows; persistent 256 blocks x 2 items.
// No-max exp2 softmax (scale log2e/32 baked in), l via P @ ones.
// smem: K0@0 K1@9216 K2@18432 | V0@27648 V1@36864 V2@46080 (55296 B).
// Wq staged @18432 during prologue (overlaps K2; safe — K tile 2 is
// issued only after the post-pack barrier).
// =================================================================
__global__ void __launch_bounds__(128, 2) attn_bf16(const float* __restrict__ Xq,
                                                    const float* __restrict__ Wq,
                                                    const __nv_bfloat16* __restrict__ K,
                                                    const __nv_bfloat16* __restrict__ V,
                                                    __nv_bfloat16* __restrict__ O)
{
    extern __shared__ __align__(16) char sm[];
    const unsigned smb = su32(sm);

    const int tid  = threadIdx.x;
    const int wid  = tid >> 5;     // 0..3
    const int lane = tid & 31;
    const int lr   = lane >> 2;
    const int lc   = lane & 3;
    const unsigned oa = frag_oa(lane), ob = frag_ob(lane);
    const unsigned ONES = 0x3F803F80u;   // bf16x2 {1.0, 1.0}
    const float qscale = 0.045084220f;   // log2e / 32

    for (int item = 0; item < 2; item++) {
        const int idx = blockIdx.x + item * 256;   // 0..511
        const int qt = idx & 15;
        const int h  = (idx >> 4) & 15;
        const int n  = idx >> 8;
        const int qbase = qt * 128;

        const float* Xg = Xq + ((size_t)(n * LSEQ + qbase)) * EMB + h * HDIM;
        const __nv_bfloat16* Kg = K + ((size_t)n * LSEQ) * EMB + h * HDIM;
        const __nv_bfloat16* Vg = V + ((size_t)n * LSEQ) * EMB + h * HDIM;

        __syncthreads();   // prior item fully consumed smem (no-op on item 0)

        // ---- stage Wq (64x64 fp32 -> bf16) @18432 ----
        #pragma unroll
        for (int it = 0; it < 8; it++) {
            int i = tid + it * 128;
            int r = i >> 4, g = i & 15;
            float4 v = *(const float4*)(Wq + (size_t)r * 64 + 4 * g);
            *(uint2*)(sm + 18432 + r * 144 + g * 8) = make_uint2(packbf(v.x, v.y), packbf(v.z, v.w));
        }
        __syncthreads();

        // ---- per-warp Q projection: X frags direct from gmem ----
        unsigned xa[2][4][4];
        #pragma unroll
        for (int g = 0; g < 2; g++)
            #pragma unroll
            for (int ks = 0; ks < 4; ks++)
                load_afrag(xa[g][ks], Xg + (size_t)(wid * 32 + g * 16) * EMB,
                           EMB, ks, lr, lc);

        float qa[2][8][4];
        #pragma unroll
        for (int g = 0; g < 2; g++)
            #pragma unroll
            for (int nt = 0; nt < 8; nt++)
                #pragma unroll
                for (int j = 0; j < 4; j++) qa[g][nt][j] = 0.f;

        #pragma unroll
        for (int nt = 0; nt < 8; nt++) {
            unsigned b0, b1, b2, b3, c0, c1, c2, c3;
            ldsm4(b0, b1, b2, b3, smb + 18432 + nt * 1152 + ob);
            ldsm4(c0, c1, c2, c3, smb + 18432 + nt * 1152 + 64 + ob);
            #pragma unroll
            for (int g = 0; g < 2; g++) {
                mma16(qa[g][nt], xa[g][0], b0, b1);
                mma16(qa[g][nt], xa[g][1], b2, b3);
                mma16(qa[g][nt], xa[g][2], c0, c1);
                mma16(qa[g][nt], xa[g][3], c2, c3);
            }
        }

        // pack proj C-fragments -> QK^T A-fragments (scale baked in)
        unsigned aq[2][4][4];
        #pragma unroll
        for (int g = 0; g < 2; g++)
            #pragma unroll
            for (int ks = 0; ks < 4; ks++) {
                aq[g][ks][0] = packbf(qa[g][2 * ks][0] * qscale,     qa[g][2 * ks][1] * qscale);
                aq[g][ks][1] = packbf(qa[g][2 * ks][2] * qscale,     qa[g][2 * ks][3] * qscale);
                aq[g][ks][2] = packbf(qa[g][2 * ks + 1][0] * qscale, qa[g][2 * ks + 1][1] * qscale);
                aq[g][ks][3] = packbf(qa[g][2 * ks + 1][2] * qscale, qa[g][2 * ks + 1][3] * qscale);
            }
        __syncthreads();   // all warps done with Wq smem before K tile 2 lands

        // ---- issue K/V tiles 0 and 1 ----
        #pragma unroll
        for (int t = 0; t < 2; t++) {
            #pragma unroll
            for (int it = 0; it < 4; it++) {
                int i = tid + it * 128;  int r = i >> 3, c = i & 7;
                cpasync16(smb + t * 9216 + r * 144 + c * 16,
                          Kg + (size_t)(t * 64 + r) * EMB + c * 8);
                cpasync16(smb + 27648 + t * 9216 + r * 144 + c * 16,
                          Vg + (size_t)(t * 64 + r) * EMB + c * 8);
            }
            cp_commit();
        }

        float lacc[2][4];
        float o[2][8][4];
        #pragma unroll
        for (int g = 0; g < 2; g++) {
            #pragma unroll
            for (int j = 0; j < 4; j++) lacc[g][j] = 0.f;
            #pragma unroll
            for (int nt = 0; nt < 8; nt++)
                #pragma unroll
                for (int j = 0; j < 4; j++) o[g][nt][j] = 0.f;
        }

        for (int kt = 0; kt < 32; kt++) {
            if (kt < 31) cp_wait1(); else cp_wait0();
            __syncthreads();   // tile kt visible; all warps done with buf[(kt-1)%3]

            if (kt + 2 < 32) {
                const int t = kt + 2;
                const unsigned kb2 = (unsigned)(t % 3) * 9216;
                #pragma unroll
                for (int it = 0; it < 4; it++) {
                    int i = tid + it * 128;  int r = i >> 3, c = i & 7;
                    cpasync16(smb + kb2 + r * 144 + c * 16,
                              Kg + (size_t)(t * 64 + r) * EMB + c * 8);
                    cpasync16(smb + 27648 + kb2 + r * 144 + c * 16,
                              Vg + (size_t)(t * 64 + r) * EMB + c * 8);
                }
                cp_commit();
            }

            const unsigned kb = (unsigned)(kt % 3) * 9216;
            const unsigned vb = 27648 + kb;

            // ---- S = Q(32x64) @ K^T(64x64): K frags shared across groups ----
            float s0[8][4], s1[8][4];
            #pragma unroll
            for (int nt = 0; nt < 8; nt++)
                #pragma unroll
                for (int j = 0; j < 4; j++) { s0[nt][j] = 0.f; s1[nt][j] = 0.f; }

            #pragma unroll
            for (int nt = 0; nt < 8; nt++) {
                unsigned b0, b1, b2, b3, c0, c1, c2, c3;
                ldsm4(b0, b1, b2, b3, smb + kb + nt * 1152 + ob);
                ldsm4(c0, c1, c2, c3, smb + kb + nt * 1152 + 64 + ob);
                mma16(s0[nt], aq[0][0], b0, b1);
                mma16(s0[nt], aq[0][1], b2, b3);
                mma16(s0[nt], aq[0][2], c0, c1);
                mma16(s0[nt], aq[0][3], c2, c3);
                mma16(s1[nt], aq[1][0], b0, b1);
                mma16(s1[nt], aq[1][1], b2, b3);
                mma16(s1[nt], aq[1][2], c0, c1);
                mma16(s1[nt], aq[1][3], c2, c3);
            }

            // ---- P = 2^S in bf16x2 domain; A-fragments direct from registers ----
            unsigned ap0[4][4], ap1[4][4];
            #pragma unroll
            for (int ks = 0; ks < 4; ks++) {
                ap0[ks][0] = ex2b(packbf(s0[2 * ks][0],     s0[2 * ks][1]));
                ap0[ks][1] = ex2b(packbf(s0[2 * ks][2],     s0[2 * ks][3]));
                ap0[ks][2] = ex2b(packbf(s0[2 * ks + 1][0], s0[2 * ks + 1][1]));
                ap0[ks][3] = ex2b(packbf(s0[2 * ks + 1][2], s0[2 * ks + 1][3]));
                ap1[ks][0] = ex2b(packbf(s1[2 * ks][0],     s1[2 * ks][1]));
                ap1[ks][1] = ex2b(packbf(s1[2 * ks][2],     s1[2 * ks][3]));
                ap1[ks][2] = ex2b(packbf(s1[2 * ks + 1][0], s1[2 * ks + 1][1]));
                ap1[ks][3] = ex2b(packbf(s1[2 * ks + 1][2], s1[2 * ks + 1][3]));
            }

            // ---- l += P @ ones ----
            #pragma unroll
            for (int ks = 0; ks < 4; ks++) {
                mma16(lacc[0], ap0[ks], ONES, ONES);
                mma16(lacc[1], ap1[ks], ONES, ONES);
            }

            // ---- O += P(32x64) @ V(64x64): V frags shared across groups ----
            #pragma unroll
            for (int ntp = 0; ntp < 4; ntp++) {
                #pragma unroll
                for (int ks = 0; ks < 4; ks++) {
                    unsigned v0, v1, v2, v3;
                    ldsm4t(v0, v1, v2, v3, smb + vb + ks * 2304 + ntp * 32 + oa);
                    mma16(o[0][2 * ntp],     ap0[ks], v0, v1);
                    mma16(o[0][2 * ntp + 1], ap0[ks], v2, v3);
                    mma16(o[1][2 * ntp],     ap1[ks], v0, v1);
                    mma16(o[1][2 * ntp + 1], ap1[ks], v2, v3);
                }
            }
        }

        // ---- normalize + store bf16 (lacc[g][0]=row lr, [2]=row lr+8) ----
        unsigned* O32 = (unsigned*)O;
        #pragma unroll
        for (int g = 0; g < 2; g++) {
            const float inv_lo = 1.f / lacc[g][0];
            const float inv_hi = 1.f / lacc[g][2];
            const int r_lo = qbase + wid * 32 + g * 16 + lr;
            const size_t base_lo = ((size_t)(n * LSEQ + r_lo)) * (EMB / 2) + h * 32;
            const size_t base_hi = base_lo + 8 * (EMB / 2);
            #pragma unroll
            for (int nt = 0; nt < 8; nt++) {
                O32[base_lo + nt * 4 + lc] = packbf(o[g][nt][0] * inv_lo, o[g][nt][1] * inv_lo);
                O32[base_hi + nt * 4 + lc] = packbf(o[g][nt][2] * inv_hi, o[g][nt][3] * inv_hi);
            }
        }
    }
}

// =================================================================
// Kernel 3: out = A(4096x1024,bf16) @ Wo16^T + bo, fp32 out.
// Block 128x128, 8 warps (4M x 2N), kc=32, 3-stage ring, 80B rows.
// =================================================================
__global__ void __launch_bounds__(256, 2) out_bf16(const __nv_bfloat16* __restrict__ A,
                                                   const __nv_bfloat16* __restrict__ W,
                                                   const float* __restrict__ bo,
                                                   float* __restrict__ out)
{
    extern __shared__ __align__(16) char smo[];
    const unsigned smb = su32(smo);

    const int tid  = threadIdx.x;
    const int wid  = tid >> 5;
    const int lane = tid & 31;
    const int lr   = lane >> 2;
    const int lc   = lane & 3;
    const int row0 = blockIdx.x * 128;
    const int col0 = blockIdx.y * 128;
    const int wm   = wid & 3;
    const int wn   = wid >> 2;
    const unsigned oa = frag_oa80(lane), ob = frag_ob80(lane);

    #pragma unroll
    for (int t = 0; t < 2; t++) {
        const unsigned base = (unsigned)t * 20480;
        #pragma unroll
        for (int it = 0; it < 2; it++) {
            int i = tid + it * 256;  int r = i >> 2, c = i & 3;
            cpasync16(smb + base + r * 80 + c * 16,
                      A + (size_t)(row0 + r) * EMB + t * 32 + c * 8);
            cpasync16(smb + base + 10240 + r * 80 + c * 16,
                      W + (size_t)(col0 + r) * EMB + t * 32 + c * 8);
        }
        cp_commit();
    }

    float acc[2][8][4];
    #pragma unroll
    for (int mt = 0; mt < 2; mt++)
        #pragma unroll
        for (int nt = 0; nt < 8; nt++)
            #pragma unroll
            for (int j = 0; j < 4; j++) acc[mt][nt][j] = 0.f;

    for (int kb = 0; kb < 32; kb++) {
        if (kb < 31) cp_wait1(); else cp_wait0();
        __syncthreads();

        if (kb + 2 < 32) {
            const int t = kb + 2;
            const unsigned base = (unsigned)(t % 3) * 20480;
            #pragma unroll
            for (int it = 0; it < 2; it++) {
                int i = tid + it * 256;  int r = i >> 2, c = i & 3;
                cpasync16(smb + base + r * 80 + c * 16,
                          A + (size_t)(row0 + r) * EMB + t * 32 + c * 8);
                cpasync16(smb + base + 10240 + r * 80 + c * 16,
                          W + (size_t)(col0 + r) * EMB + t * 32 + c * 8);
            }
            cp_commit();
        }

        const unsigned ab = (unsigned)(kb % 3) * 20480;
        const unsigned wb = ab + 10240;

        unsigned aa[2][2][4];
        #pragma unroll
        for (int mt = 0; mt < 2; mt++)
            #pragma unroll
            for (int kh = 0; kh < 2; kh++)
                ldsm4(aa[mt][kh][0], aa[mt][kh][1], aa[mt][kh][2], aa[mt][kh][3],
                      smb + ab + (wm * 32 + mt * 16) * 80 + kh * 32 + oa);

        #pragma unroll
        for (int nt = 0; nt < 8; nt++) {
            unsigned b0, b1, b2, b3;
            ldsm4(b0, b1, b2, b3, smb + wb + (wn * 64 + nt * 8) * 80 + ob);
            mma16(acc[0][nt], aa[0][0], b0, b1);
            mma16(acc[0][nt], aa[0][1], b2, b3);
            mma16(acc[1][nt], aa[1][0], b0, b1);
            mma16(acc[1][nt], aa[1][1], b2, b3);
        }
    }

    #pragma unroll
    for (int mt = 0; mt < 2; mt++) {
        const int rlo = row0 + wm * 32 + mt * 16 + lr;
        #pragma unroll
        for (int nt = 0; nt < 8; nt++) {
            const int c = col0 + wn * 64 + nt * 8 + 2 * lc;
            float2 b = *(const float2*)(bo + c);
            *(float2*)(out + (size_t)rlo * EMB + c) =
                make_float2(acc[mt][nt][0] + b.x, acc[mt][nt][1] + b.y);
            *(float2*)(out + (size_t)(rlo + 8) * EMB + c) =
                make_float2(acc[mt][nt][2] + b.x, acc[mt][nt][3] + b.y);
        }
    }
}

// =================================================================
// launch
// =================================================================
extern "C" void kernel_launch(void* const* d_in, const int* in_sizes, int n_in,
                              void* d_out, int out_size)
{
    const float* values  = (const float*)d_in[0];
    const float* keys    = (const float*)d_in[1];
    const float* queries = (const float*)d_in[2];
    const float* Wv      = (const float*)d_in[3];
    const float* Wk      = (const float*)d_in[4];
    const float* Wq      = (const float*)d_in[5];
    const float* Wo      = (const float*)d_in[6];
    const float* bo      = (const float*)d_in[7];
    float* out = (float*)d_out;

    __nv_bfloat16 *k_p, *v_p, *att_p, *wo_p;
    cudaGetSymbolAddress((void**)&k_p,   g_k);
    cudaGetSymbolAddress((void**)&v_p,   g_v);
    cudaGetSymbolAddress((void**)&att_p, g_att);
    cudaGetSymbolAddress((void**)&wo_p,  g_wo);

    // K/V projections (256 rows/block, no X staging) + Wo cvt
    proj_bf16<<<dim3(256, 3), 256>>>(keys,   Wk, k_p,
                                     values, Wv, v_p,
                                     Wo, wo_p);

    // flash attention w/ fused Q projection: persistent 256 blocks x 2 items
    cudaFuncSetAttribute(attn_bf16, cudaFuncAttributeMaxDynamicSharedMemorySize, 55296);
    attn_bf16<<<256, 128, 55296>>>(queries, Wq, k_p, v_p, att_p);

    // output projection (61440 B dynamic smem, 3-stage ring)
    cudaFuncSetAttribute(out_bf16, cudaFuncAttributeMaxDynamicSharedMemorySize, 61440);
    out_bf16<<<dim3((NB * LSEQ) / 128, EMB / 128), 256, 61440>>>(att_p, wo_p, bo, out);
}

// round 16
// speedup vs baseline: 1.0149x; 1.0149x over previous
#include <cuda_runtime.h>
#include <cuda_bf16.h>
#include <math.h>

#define NB    2
#define LSEQ  2048
#define EMB   1024
#define HEADS 16
#define HDIM  64

// ---------------- scratch (no allocations allowed) ----------------
__device__ __align__(16) __nv_bfloat16 g_k[NB * LSEQ * EMB];
__device__ __align__(16) __nv_bfloat16 g_v[NB * LSEQ * EMB];
__device__ __align__(16) __nv_bfloat16 g_att[NB * LSEQ * EMB];
__device__ __align__(16) __nv_bfloat16 g_wo[EMB * EMB];

// ---------------- helpers ----------------
__device__ __forceinline__ unsigned su32(const void* p) {
    return (unsigned)__cvta_generic_to_shared(p);
}
__device__ __forceinline__ unsigned packbf(float lo, float hi) {
    __nv_bfloat162 t = __floats2bfloat162_rn(lo, hi);   // .x = lo (low 16 bits)
    return *reinterpret_cast<unsigned*>(&t);
}
__device__ __forceinline__ unsigned ex2b(unsigned x) {   // exp2 on packed bf16x2
    unsigned r;
    asm("ex2.approx.ftz.bf16x2 %0, %1;" : "=r"(r) : "r"(x));
    return r;
}
// D(16x8,f32) += A(16x16,bf16) * B(16x8,bf16)
__device__ __forceinline__ void mma16(float* c, const unsigned* a, unsigned b0, unsigned b1) {
    asm volatile(
        "mma.sync.aligned.m16n8k16.row.col.f32.bf16.bf16.f32 "
        "{%0,%1,%2,%3}, {%4,%5,%6,%7}, {%8,%9}, {%0,%1,%2,%3};\n"
        : "+f"(c[0]), "+f"(c[1]), "+f"(c[2]), "+f"(c[3])
        : "r"(a[0]), "r"(a[1]), "r"(a[2]), "r"(a[3]), "r"(b0), "r"(b1));
}
__device__ __forceinline__ void ldsm4(unsigned& a, unsigned& b, unsigned& c, unsigned& d, unsigned addr) {
    asm volatile("ldmatrix.sync.aligned.m8n8.x4.shared.b16 {%0,%1,%2,%3}, [%4];"
                 : "=r"(a), "=r"(b), "=r"(c), "=r"(d) : "r"(addr));
}
__device__ __forceinline__ void ldsm4t(unsigned& a, unsigned& b, unsigned& c, unsigned& d, unsigned addr) {
    asm volatile("ldmatrix.sync.aligned.m8n8.x4.trans.shared.b16 {%0,%1,%2,%3}, [%4];"
                 : "=r"(a), "=r"(b), "=r"(c), "=r"(d) : "r"(addr));
}
__device__ __forceinline__ void cpasync16(unsigned dst, const void* src) {
    asm volatile("cp.async.cg.shared.global [%0], [%1], 16;" :: "r"(dst), "l"(src));
}
__device__ __forceinline__ void cp_commit() { asm volatile("cp.async.commit_group;"); }
__device__ __forceinline__ void cp_wait0() { asm volatile("cp.async.wait_group 0;" ::: "memory"); }
__device__ __forceinline__ void cp_wait1() { asm volatile("cp.async.wait_group 1;" ::: "memory"); }

// fragment offsets for 144B-stride tiles (64 bf16 + 8 pad)
__device__ __forceinline__ unsigned frag_oa(int lane) {   // A-frag / V-trans ldsm.x4
    return ((((lane >> 3) & 1) * 8 + (lane & 7)) * 144) + ((lane >> 4) * 16);
}
__device__ __forceinline__ unsigned frag_ob(int lane) {   // B-frag non-trans ldsm.x4
    return (lane & 7) * 144 + ((lane >> 3) & 3) * 16;
}
// fragment offsets for 80B-stride tiles (32 bf16 + 8 pad)
__device__ __forceinline__ unsigned frag_oa80(int lane) {
    return ((((lane >> 3) & 1) * 8 + (lane & 7)) * 80) + ((lane >> 4) * 16);
}
__device__ __forceinline__ unsigned frag_ob80(int lane) {
    return (lane & 7) * 80 + ((lane >> 3) & 3) * 16;
}

// Load one m16n8k16 A-fragment k-step straight from gmem (fp32 row-major,
// `stride` floats per row) into packed bf16 regs.
__device__ __forceinline__ void load_afrag(unsigned* a, const float* base,
                                           int stride, int ks, int lr, int lc) {
    const float* p0 = base + (size_t)lr * stride + ks * 16 + 2 * lc;
    const float* p1 = base + (size_t)(lr + 8) * stride + ks * 16 + 2 * lc;
    float2 a0 = *(const float2*)(p0);
    float2 a1 = *(const float2*)(p1);
    float2 a2 = *(const float2*)(p0 + 8);
    float2 a3 = *(const float2*)(p1 + 8);
    a[0] = packbf(a0.x, a0.y);
    a[1] = packbf(a1.x, a1.y);
    a[2] = packbf(a2.x, a2.y);
    a[3] = packbf(a3.x, a3.y);
}

// =================================================================
// Kernel 1: K/V per-head projections (bf16 MMA), bf16 out.
// HIGH OCCUPANCY: 16 rows/warp (128 rows/block), X direct from gmem,
// only W (9KB) in smem, __launch_bounds__(256,3) -> 3 CTAs/SM.
// grid.y: 0=K, 1=V, 2=Wo fp32->bf16 cvt.  (Q proj fused into attn.)
// =================================================================
__global__ void __launch_bounds__(256, 3) proj_bf16(
    const float* __restrict__ xk, const float* __restrict__ Wk, __nv_bfloat16* __restrict__ yk,
    const float* __restrict__ xv, const float* __restrict__ Wv, __nv_bfloat16* __restrict__ yv,
    const float* __restrict__ Wo, __nv_bfloat16* __restrict__ wo16)
{
    if (blockIdx.y == 2) {   // Wo conversion: 512 blocks * 256 thr * 8 = 1M elems
        if (blockIdx.x >= 512) return;
        size_t i = ((size_t)blockIdx.x * 256 + threadIdx.x) * 8;
        float4 a = *(const float4*)(Wo + i);
        float4 b = *(const float4*)(Wo + i + 4);
        uint4 o;
        o.x = packbf(a.x, a.y);  o.y = packbf(a.z, a.w);
        o.z = packbf(b.x, b.y);  o.w = packbf(b.z, b.w);
        *(uint4*)(wo16 + i) = o;
        return;
    }

    __shared__ __align__(16) char sm[9216];   // Ws 64x144 only
    const unsigned smb = su32(sm);

    const float* x; const float* W; __nv_bfloat16* y;
    if (blockIdx.y == 0) { x = xk; W = Wk; y = yk; }
    else                 { x = xv; W = Wv; y = yv; }

    const int tid  = threadIdx.x;
    const int wid  = tid >> 5;
    const int lane = tid & 31;
    const int lr   = lane >> 2;
    const int lc   = lane & 3;
    const int row0 = blockIdx.x * 128;
    const unsigned ob = frag_ob(lane);

    // stage W (64x64 fp32 -> bf16)
    #pragma unroll
    for (int it = 0; it < 4; it++) {
        int i = tid + it * 256;
        int r = i >> 4, g = i & 15;
        float4 v = *(const float4*)(W + (size_t)r * 64 + 4 * g);
        *(uint2*)(sm + r * 144 + g * 8) = make_uint2(packbf(v.x, v.y), packbf(v.z, v.w));
    }
    __syncthreads();

    // X fragments: 16 rows per warp, direct from gmem
    unsigned aq[4][4];
    #pragma unroll
    for (int ks = 0; ks < 4; ks++)
        load_afrag(aq[ks], x + (size_t)(row0 + wid * 16) * 64, 64, ks, lr, lc);

    float acc[8][4];
    #pragma unroll
    for (int nt = 0; nt < 8; nt++)
        #pragma unroll
        for (int j = 0; j < 4; j++) acc[nt][j] = 0.f;

    #pragma unroll
    for (int nt = 0; nt < 8; nt++) {
        unsigned b0, b1, b2, b3, c0, c1, c2, c3;
        ldsm4(b0, b1, b2, b3, smb + nt * 1152 + ob);
        ldsm4(c0, c1, c2, c3, smb + nt * 1152 + 64 + ob);
        mma16(acc[nt], aq[0], b0, b1);
        mma16(acc[nt], aq[1], b2, b3);
        mma16(acc[nt], aq[2], c0, c1);
        mma16(acc[nt], aq[3], c2, c3);
    }

    const int rlo = row0 + wid * 16 + lr;
    unsigned* y32 = (unsigned*)y;
    #pragma unroll
    for (int nt = 0; nt < 8; nt++) {
        y32[(size_t)rlo * 32 + nt * 4 + lc] = packbf(acc[nt][0], acc[nt][1]);
        y32[(size_t)(rlo + 8) * 32 + nt * 4 + lc] = packbf(acc[nt][2], acc[nt][3]);
    }
}

// =================================================================
// Kernel 2: flash attention with FUSED Q projection (round-11 best).
// 4 warps x 32 q-rows; persistent 256 blocks x 2 items.
// No-max exp2 softmax (scale log2e/32 baked in), l via P @ ones.
// smem: K0@0 K1@9216 K2@18432 | V0@27648 V1@36864 V2@46080 (55296 B).
// Prologue X@0 (18432), Wq@18432 (9216) overlap K buffers.
// =================================================================
__global__ void __launch_bounds__(128, 2) attn_bf16(const float* __restrict__ Xq,
                                                    const float* __restrict__ Wq,
                                                    const __nv_bfloat16* __restrict__ K,
                                                    const __nv_bfloat16* __restrict__ V,
                                                    __nv_bfloat16* __restrict__ O)
{
    extern __shared__ __align__(16) char sm[];
    const unsigned smb = su32(sm);

    const int tid  = threadIdx.x;
    const int wid  = tid >> 5;     // 0..3
    const int lane = tid & 31;
    const int lr   = lane >> 2;
    const int lc   = lane & 3;
    const unsigned oa = frag_oa(lane), ob = frag_ob(lane);
    const unsigned ONES = 0x3F803F80u;   // bf16x2 {1.0, 1.0}
    const float qscale = 0.045084220f;   // log2e / 32

    for (int item = 0; item < 2; item++) {
        const int idx = blockIdx.x + item * 256;   // 0..511
        const int qt = idx & 15;
        const int h  = (idx >> 4) & 15;
        const int n  = idx >> 8;
        const int qbase = qt * 128;

        const float* Xg = Xq + ((size_t)(n * LSEQ + qbase)) * EMB + h * HDIM;
        const __nv_bfloat16* Kg = K + ((size_t)n * LSEQ) * EMB + h * HDIM;
        const __nv_bfloat16* Vg = V + ((size_t)n * LSEQ) * EMB + h * HDIM;

        __syncthreads();   // prior item fully consumed smem (no-op on item 0)

        // ---- stage x_q (128x64 fp32 -> bf16) @0 and Wq (64x64) @18432 ----
        #pragma unroll
        for (int it = 0; it < 16; it++) {
            int i = tid + it * 128;
            int r = i >> 4, g = i & 15;
            float4 v = *(const float4*)(Xg + (size_t)r * EMB + 4 * g);
            *(uint2*)(sm + r * 144 + g * 8) = make_uint2(packbf(v.x, v.y), packbf(v.z, v.w));
        }
        #pragma unroll
        for (int it = 0; it < 8; it++) {
            int i = tid + it * 128;
            int r = i >> 4, g = i & 15;
            float4 v = *(const float4*)(Wq + (size_t)r * 64 + 4 * g);
            *(uint2*)(sm + 18432 + r * 144 + g * 8) = make_uint2(packbf(v.x, v.y), packbf(v.z, v.w));
        }
        __syncthreads();

        // ---- per-warp Q projection: rows wid*32 .. wid*32+31 ----
        unsigned xa[2][4][4];
        #pragma unroll
        for (int g = 0; g < 2; g++)
            #pragma unroll
            for (int ks = 0; ks < 4; ks++)
                ldsm4(xa[g][ks][0], xa[g][ks][1], xa[g][ks][2], xa[g][ks][3],
                      smb + (wid * 32 + g * 16) * 144 + ks * 32 + oa);

        float qa[2][8][4];
        #pragma unroll
        for (int g = 0; g < 2; g++)
            #pragma unroll
            for (int nt = 0; nt < 8; nt++)
                #pragma unroll
                for (int j = 0; j < 4; j++) qa[g][nt][j] = 0.f;

        #pragma unroll
        for (int nt = 0; nt < 8; nt++) {
            unsigned b0, b1, b2, b3, c0, c1, c2, c3;
            ldsm4(b0, b1, b2, b3, smb + 18432 + nt * 1152 + ob);
            ldsm4(c0, c1, c2, c3, smb + 18432 + nt * 1152 + 64 + ob);
            #pragma unroll
            for (int g = 0; g < 2; g++) {
                mma16(qa[g][nt], xa[g][0], b0, b1);
                mma16(qa[g][nt], xa[g][1], b2, b3);
                mma16(qa[g][nt], xa[g][2], c0, c1);
                mma16(qa[g][nt], xa[g][3], c2, c3);
            }
        }

        // pack proj C-fragments -> QK^T A-fragments (scale baked in)
        unsigned aq[2][4][4];
        #pragma unroll
        for (int g = 0; g < 2; g++)
            #pragma unroll
            for (int ks = 0; ks < 4; ks++) {
                aq[g][ks][0] = packbf(qa[g][2 * ks][0] * qscale,     qa[g][2 * ks][1] * qscale);
                aq[g][ks][1] = packbf(qa[g][2 * ks][2] * qscale,     qa[g][2 * ks][3] * qscale);
                aq[g][ks][2] = packbf(qa[g][2 * ks + 1][0] * qscale, qa[g][2 * ks + 1][1] * qscale);
                aq[g][ks][3] = packbf(qa[g][2 * ks + 1][2] * qscale, qa[g][2 * ks + 1][3] * qscale);
            }
        __syncthreads();   // all warps done with X/Wq smem before K overwrites

        // ---- issue K/V tiles 0 and 1 ----
        #pragma unroll
        for (int t = 0; t < 2; t++) {
            #pragma unroll
            for (int it = 0; it < 4; it++) {
                int i = tid + it * 128;  int r = i >> 3, c = i & 7;
                cpasync16(smb + t * 9216 + r * 144 + c * 16,
                          Kg + (size_t)(t * 64 + r) * EMB + c * 8);
                cpasync16(smb + 27648 + t * 9216 + r * 144 + c * 16,
                          Vg + (size_t)(t * 64 + r) * EMB + c * 8);
            }
            cp_commit();
        }

        float lacc[2][4];
        float o[2][8][4];
        #pragma unroll
        for (int g = 0; g < 2; g++) {
            #pragma unroll
            for (int j = 0; j < 4; j++) lacc[g][j] = 0.f;
            #pragma unroll
            for (int nt = 0; nt < 8; nt++)
                #pragma unroll
                for (int j = 0; j < 4; j++) o[g][nt][j] = 0.f;
        }

        for (int kt = 0; kt < 32; kt++) {
            if (kt < 31) cp_wait1(); else cp_wait0();
            __syncthreads();   // tile kt visible; all warps done with buf[(kt-1)%3]

            if (kt + 2 < 32) {
                const int t = kt + 2;
                const unsigned kb2 = (unsigned)(t % 3) * 9216;
                #pragma unroll
                for (int it = 0; it < 4; it++) {
                    int i = tid + it * 128;  int r = i >> 3, c = i & 7;
                    cpasync16(smb + kb2 + r * 144 + c * 16,
                              Kg + (size_t)(t * 64 + r) * EMB + c * 8);
                    cpasync16(smb + 27648 + kb2 + r * 144 + c * 16,
                              Vg + (size_t)(t * 64 + r) * EMB + c * 8);
                }
                cp_commit();
            }

            const unsigned kb = (unsigned)(kt % 3) * 9216;
            const unsigned vb = 27648 + kb;

            // ---- S = Q(32x64) @ K^T(64x64): K frags shared across groups ----
            float s0[8][4], s1[8][4];
            #pragma unroll
            for (int nt = 0; nt < 8; nt++)
                #pragma unroll
                for (int j = 0; j < 4; j++) { s0[nt][j] = 0.f; s1[nt][j] = 0.f; }

            #pragma unroll
            for (int nt = 0; nt < 8; nt++) {
                unsigned b0, b1, b2, b3, c0, c1, c2, c3;
                ldsm4(b0, b1, b2, b3, smb + kb + nt * 1152 + ob);
                ldsm4(c0, c1, c2, c3, smb + kb + nt * 1152 + 64 + ob);
                mma16(s0[nt], aq[0][0], b0, b1);
                mma16(s0[nt], aq[0][1], b2, b3);
                mma16(s0[nt], aq[0][2], c0, c1);
                mma16(s0[nt], aq[0][3], c2, c3);
                mma16(s1[nt], aq[1][0], b0, b1);
                mma16(s1[nt], aq[1][1], b2, b3);
                mma16(s1[nt], aq[1][2], c0, c1);
                mma16(s1[nt], aq[1][3], c2, c3);
            }

            // ---- P = 2^S in bf16x2 domain; A-fragments direct from registers ----
            unsigned ap0[4][4], ap1[4][4];
            #pragma unroll
            for (int ks = 0; ks < 4; ks++) {
                ap0[ks][0] = ex2b(packbf(s0[2 * ks][0],     s0[2 * ks][1]));
                ap0[ks][1] = ex2b(packbf(s0[2 * ks][2],     s0[2 * ks][3]));
                ap0[ks][2] = ex2b(packbf(s0[2 * ks + 1][0], s0[2 * ks + 1][1]));
                ap0[ks][3] = ex2b(packbf(s0[2 * ks + 1][2], s0[2 * ks + 1][3]));
                ap1[ks][0] = ex2b(packbf(s1[2 * ks][0],     s1[2 * ks][1]));
                ap1[ks][1] = ex2b(packbf(s1[2 * ks][2],     s1[2 * ks][3]));
                ap1[ks][2] = ex2b(packbf(s1[2 * ks + 1][0], s1[2 * ks + 1][1]));
                ap1[ks][3] = ex2b(packbf(s1[2 * ks + 1][2], s1[2 * ks + 1][3]));
            }

            // ---- l += P @ ones ----
            #pragma unroll
            for (int ks = 0; ks < 4; ks++) {
                mma16(lacc[0], ap0[ks], ONES, ONES);
                mma16(lacc[1], ap1[ks], ONES, ONES);
            }

            // ---- O += P(32x64) @ V(64x64): V frags shared across groups ----
            #pragma unroll
            for (int ntp = 0; ntp < 4; ntp++) {
                #pragma unroll
                for (int ks = 0; ks < 4; ks++) {
                    unsigned v0, v1, v2, v3;
                    ldsm4t(v0, v1, v2, v3, smb + vb + ks * 2304 + ntp * 32 + oa);
                    mma16(o[0][2 * ntp],     ap0[ks], v0, v1);
                    mma16(o[0][2 * ntp + 1], ap0[ks], v2, v3);
                    mma16(o[1][2 * ntp],     ap1[ks], v0, v1);
                    mma16(o[1][2 * ntp + 1], ap1[ks], v2, v3);
                }
            }
        }

        // ---- normalize + store bf16 (lacc[g][0]=row lr, [2]=row lr+8) ----
        unsigned* O32 = (unsigned*)O;
        #pragma unroll
        for (int g = 0; g < 2; g++) {
            const float inv_lo = 1.f / lacc[g][0];
            const float inv_hi = 1.f / lacc[g][2];
            const int r_lo = qbase + wid * 32 + g * 16 + lr;
            const size_t base_lo = ((size_t)(n * LSEQ + r_lo)) * (EMB / 2) + h * 32;
            const size_t base_hi = base_lo + 8 * (EMB / 2);
            #pragma unroll
            for (int nt = 0; nt < 8; nt++) {
                O32[base_lo + nt * 4 + lc] = packbf(o[g][nt][0] * inv_lo, o[g][nt][1] * inv_lo);
                O32[base_hi + nt * 4 + lc] = packbf(o[g][nt][2] * inv_hi, o[g][nt][3] * inv_hi);
            }
        }
    }
}

// =================================================================
// Kernel 3: out = A(4096x1024,bf16) @ Wo16^T + bo, fp32 out.
// Block 128x128, 8 warps (4M x 2N), kc=32, 3-stage ring, 80B rows.
// =================================================================
__global__ void __launch_bounds__(256, 2) out_bf16(const __nv_bfloat16* __restrict__ A,
                                                   const __nv_bfloat16* __restrict__ W,
                                                   const float* __restrict__ bo,
                                                   float* __restrict__ out)
{
    extern __shared__ __align__(16) char smo[];
    const unsigned smb = su32(smo);

    const int tid  = threadIdx.x;
    const int wid  = tid >> 5;
    const int lane = tid & 31;
    const int lr   = lane >> 2;
    const int lc   = lane & 3;
    const int row0 = blockIdx.x * 128;
    const int col0 = blockIdx.y * 128;
    const int wm   = wid & 3;
    const int wn   = wid >> 2;
    const unsigned oa = frag_oa80(lane), ob = frag_ob80(lane);

    #pragma unroll
    for (int t = 0; t < 2; t++) {
        const unsigned base = (unsigned)t * 20480;
        #pragma unroll
        for (int it = 0; it < 2; it++) {
            int i = tid + it * 256;  int r = i >> 2, c = i & 3;
            cpasync16(smb + base + r * 80 + c * 16,
                      A + (size_t)(row0 + r) * EMB + t * 32 + c * 8);
            cpasync16(smb + base + 10240 + r * 80 + c * 16,
                      W + (size_t)(col0 + r) * EMB + t * 32 + c * 8);
        }
        cp_commit();
    }

    float acc[2][8][4];
    #pragma unroll
    for (int mt = 0; mt < 2; mt++)
        #pragma unroll
        for (int nt = 0; nt < 8; nt++)
            #pragma unroll
            for (int j = 0; j < 4; j++) acc[mt][nt][j] = 0.f;

    for (int kb = 0; kb < 32; kb++) {
        if (kb < 31) cp_wait1(); else cp_wait0();
        __syncthreads();

        if (kb + 2 < 32) {
            const int t = kb + 2;
            const unsigned base = (unsigned)(t % 3) * 20480;
            #pragma unroll
            for (int it = 0; it < 2; it++) {
                int i = tid + it * 256;  int r = i >> 2, c = i & 3;
                cpasync16(smb + base + r * 80 + c * 16,
                          A + (size_t)(row0 + r) * EMB + t * 32 + c * 8);
                cpasync16(smb + base + 10240 + r * 80 + c * 16,
                          W + (size_t)(col0 + r) * EMB + t * 32 + c * 8);
            }
            cp_commit();
        }

        const unsigned ab = (unsigned)(kb % 3) * 20480;
        const unsigned wb = ab + 10240;

        unsigned aa[2][2][4];
        #pragma unroll
        for (int mt = 0; mt < 2; mt++)
            #pragma unroll
            for (int kh = 0; kh < 2; kh++)
                ldsm4(aa[mt][kh][0], aa[mt][kh][1], aa[mt][kh][2], aa[mt][kh][3],
                      smb + ab + (wm * 32 + mt * 16) * 80 + kh * 32 + oa);

        #pragma unroll
        for (int nt = 0; nt < 8; nt++) {
            unsigned b0, b1, b2, b3;
            ldsm4(b0, b1, b2, b3, smb + wb + (wn * 64 + nt * 8) * 80 + ob);
            mma16(acc[0][nt], aa[0][0], b0, b1);
            mma16(acc[0][nt], aa[0][1], b2, b3);
            mma16(acc[1][nt], aa[1][0], b0, b1);
            mma16(acc[1][nt], aa[1][1], b2, b3);
        }
    }

    #pragma unroll
    for (int mt = 0; mt < 2; mt++) {
        const int rlo = row0 + wm * 32 + mt * 16 + lr;
        #pragma unroll
        for (int nt = 0; nt < 8; nt++) {
            const int c = col0 + wn * 64 + nt * 8 + 2 * lc;
            float2 b = *(const float2*)(bo + c);
            *(float2*)(out + (size_t)rlo * EMB + c) =
                make_float2(acc[mt][nt][0] + b.x, acc[mt][nt][1] + b.y);
            *(float2*)(out + (size_t)(rlo + 8) * EMB + c) =
                make_float2(acc[mt][nt][2] + b.x, acc[mt][nt][3] + b.y);
        }
    }
}

// =================================================================
// launch
// =================================================================
extern "C" void kernel_launch(void* const* d_in, const int* in_sizes, int n_in,
                              void* d_out, int out_size)
{
    const float* values  = (const float*)d_in[0];
    const float* keys    = (const float*)d_in[1];
    const float* queries = (const float*)d_in[2];
    const float* Wv      = (const float*)d_in[3];
    const float* Wk      = (const float*)d_in[4];
    const float* Wq      = (const float*)d_in[5];
    const float* Wo      = (const float*)d_in[6];
    const float* bo      = (const float*)d_in[7];
    float* out = (float*)d_out;

    __nv_bfloat16 *k_p, *v_p, *att_p, *wo_p;
    cudaGetSymbolAddress((void**)&k_p,   g_k);
    cudaGetSymbolAddress((void**)&v_p,   g_v);
    cudaGetSymbolAddress((void**)&att_p, g_att);
    cudaGetSymbolAddress((void**)&wo_p,  g_wo);

    // K/V projections (128 rows/block, 3 CTAs/SM) + Wo cvt
    proj_bf16<<<dim3(512, 3), 256>>>(keys,   Wk, k_p,
                                     values, Wv, v_p,
                                     Wo, wo_p);

    // flash attention w/ fused Q projection: persistent 256 blocks x 2 items
    cudaFuncSetAttribute(attn_bf16, cudaFuncAttributeMaxDynamicSharedMemorySize, 55296);
    attn_bf16<<<256, 128, 55296>>>(queries, Wq, k_p, v_p, att_p);

    // output projection (61440 B dynamic smem, 3-stage ring)
    cudaFuncSetAttribute(out_bf16, cudaFuncAttributeMaxDynamicSharedMemorySize, 61440);
    out_bf16<<<dim3((NB * LSEQ) / 128, EMB / 128), 256, 61440>>>(att_p, wo_p, bo, out);
}